// round 8
// baseline (speedup 1.0000x reference)
#include <cuda_runtime.h>
#include <cuda_bf16.h>
#include <cstdint>

// ---------------------------------------------------------------------------
// BiLSTM: B=32, T=512, I=512, H=512, gates=4H=2048, out (32,512,1024) fp32
//
// Phase A: gx = x @ Wx^T + bx. 128x128 tile, 8x8 micro-tile, K-tile 8,
//          double-buffered smem, A-tile stored as (a,a) dup pairs -> no packs.
// Phase B: persistent scan, 2 dirs x 64 blocks x 512 threads. k split 8-way;
//          register micro-tile 1j x 4g x 4b; w dup pairs + h natural pairs in
//          smem (zero pack movs in loop); separate reduce scratch (one less
//          sync); flag-based global barrier (poll line != atomic line).
// ---------------------------------------------------------------------------

#define Bsz 32
#define Tsz 512
#define Isz 512
#define Hsz 512
#define G4  2048

#define JPB 8          // hidden units per block
#define NBLK_DIR 64    // blocks per direction
#define WJ 4104        // padded per-j stride in w_s (512*8 + 8 floats)

__device__ float g_gx[(size_t)Bsz * Tsz * G4];
__device__ float g_h[2][2][Hsz * Bsz];   // [dir][parity][j*32 + b]
__device__ __align__(128) unsigned g_ctr[2][32];   // [dir][0] used
__device__ __align__(128) unsigned g_flag[2][32];  // [dir][0] used

// ---- packed f32x2 helpers --------------------------------------------------
__device__ __forceinline__ unsigned long long fma2(unsigned long long a,
                                                   unsigned long long b,
                                                   unsigned long long c) {
    unsigned long long d;
    asm("fma.rn.f32x2 %0, %1, %2, %3;" : "=l"(d) : "l"(a), "l"(b), "l"(c));
    return d;
}
__device__ __forceinline__ unsigned long long add2(unsigned long long a,
                                                   unsigned long long b) {
    unsigned long long d;
    asm("add.rn.f32x2 %0, %1, %2;" : "=l"(d) : "l"(a), "l"(b));
    return d;
}
__device__ __forceinline__ float2 unpack2(unsigned long long v) {
    float2 r;
    asm("mov.b64 {%0, %1}, %2;" : "=f"(r.x), "=f"(r.y) : "l"(v));
    return r;
}

__device__ __forceinline__ float fast_sigmoid(float x) {
    return __fdividef(1.0f, 1.0f + __expf(-x));
}
__device__ __forceinline__ float fast_tanh(float x) {
    return 1.0f - 2.0f * __fdividef(1.0f, __expf(2.0f * x) + 1.0f);
}

// ---------------------------------------------------------------------------
// Phase A: gx = x @ Wx^T + bx
// A: [M=16384][K=512], W: [N=2048][K=512] row-major.
// 128x128 tile, 256 threads, 8x8 micro-tile, K-tile 8, double buffer.
// A-tile stored duplicated: As[k][2m],[2m+1] = a  -> multiplier pairs direct.
// ---------------------------------------------------------------------------
__global__ __launch_bounds__(256, 2) void gemm_gx(const float* __restrict__ A,
                                                  const float* __restrict__ W,
                                                  const float* __restrict__ bx) {
    __shared__ __align__(16) float As[2][8][264];  // duplicated pairs
    __shared__ __align__(16) float Bs[2][8][132];

    const int bm = blockIdx.y * 128;
    const int bn = blockIdx.x * 128;
    const int tid = threadIdx.x;
    const int lrow = tid >> 1;        // 0..127
    const int lkh = (tid & 1) * 4;    // 0 or 4
    const int ty = tid >> 4;          // 0..15
    const int tx = tid & 15;          // 0..15
    const int m0 = ty * 8;
    const int n0 = tx * 8;

    const float* Aptr = A + (size_t)(bm + lrow) * Isz + lkh;
    const float* Wptr = W + (size_t)(bn + lrow) * Isz + lkh;

    // Prologue: k-tile 0 into buffer 0.
    {
        float4 a = *(const float4*)Aptr;
        float4 w = *(const float4*)Wptr;
        *(float2*)&As[0][lkh + 0][2 * lrow] = make_float2(a.x, a.x);
        *(float2*)&As[0][lkh + 1][2 * lrow] = make_float2(a.y, a.y);
        *(float2*)&As[0][lkh + 2][2 * lrow] = make_float2(a.z, a.z);
        *(float2*)&As[0][lkh + 3][2 * lrow] = make_float2(a.w, a.w);
        Bs[0][lkh + 0][lrow] = w.x;
        Bs[0][lkh + 1][lrow] = w.y;
        Bs[0][lkh + 2][lrow] = w.z;
        Bs[0][lkh + 3][lrow] = w.w;
    }
    __syncthreads();

    unsigned long long acc[8][4];
#pragma unroll
    for (int i = 0; i < 8; i++)
#pragma unroll
        for (int q = 0; q < 4; q++) acc[i][q] = 0ull;

    int cur = 0;
    for (int kt = 1; kt <= 64; kt++) {
        float4 an = make_float4(0.f, 0.f, 0.f, 0.f);
        float4 wn = make_float4(0.f, 0.f, 0.f, 0.f);
        if (kt < 64) {
            an = *(const float4*)(Aptr + kt * 8);
            wn = *(const float4*)(Wptr + kt * 8);
        }
#pragma unroll
        for (int k = 0; k < 8; k++) {
            ulonglong2 aP0 = *(const ulonglong2*)&As[cur][k][2 * m0];
            ulonglong2 aP1 = *(const ulonglong2*)&As[cur][k][2 * m0 + 4];
            ulonglong2 aP2 = *(const ulonglong2*)&As[cur][k][2 * m0 + 8];
            ulonglong2 aP3 = *(const ulonglong2*)&As[cur][k][2 * m0 + 12];
            ulonglong2 bLo = *(const ulonglong2*)&Bs[cur][k][n0];
            ulonglong2 bHi = *(const ulonglong2*)&Bs[cur][k][n0 + 4];
            unsigned long long am[8] = {aP0.x, aP0.y, aP1.x, aP1.y,
                                        aP2.x, aP2.y, aP3.x, aP3.y};
#pragma unroll
            for (int mm = 0; mm < 8; mm++) {
                acc[mm][0] = fma2(bLo.x, am[mm], acc[mm][0]);
                acc[mm][1] = fma2(bLo.y, am[mm], acc[mm][1]);
                acc[mm][2] = fma2(bHi.x, am[mm], acc[mm][2]);
                acc[mm][3] = fma2(bHi.y, am[mm], acc[mm][3]);
            }
        }
        if (kt < 64) {
            int nxt = cur ^ 1;
            *(float2*)&As[nxt][lkh + 0][2 * lrow] = make_float2(an.x, an.x);
            *(float2*)&As[nxt][lkh + 1][2 * lrow] = make_float2(an.y, an.y);
            *(float2*)&As[nxt][lkh + 2][2 * lrow] = make_float2(an.z, an.z);
            *(float2*)&As[nxt][lkh + 3][2 * lrow] = make_float2(an.w, an.w);
            Bs[nxt][lkh + 0][lrow] = wn.x;
            Bs[nxt][lkh + 1][lrow] = wn.y;
            Bs[nxt][lkh + 2][lrow] = wn.z;
            Bs[nxt][lkh + 3][lrow] = wn.w;
        }
        __syncthreads();
        cur ^= 1;
    }

    float4 bxLo = *(const float4*)&bx[bn + n0];
    float4 bxHi = *(const float4*)&bx[bn + n0 + 4];
#pragma unroll
    for (int mm = 0; mm < 8; mm++) {
        float2 p0 = unpack2(acc[mm][0]);
        float2 p1 = unpack2(acc[mm][1]);
        float2 p2 = unpack2(acc[mm][2]);
        float2 p3 = unpack2(acc[mm][3]);
        float4 r0 = make_float4(p0.x + bxLo.x, p0.y + bxLo.y,
                                p1.x + bxLo.z, p1.y + bxLo.w);
        float4 r1 = make_float4(p2.x + bxHi.x, p2.y + bxHi.y,
                                p3.x + bxHi.z, p3.y + bxHi.w);
        float* dst = &g_gx[(size_t)(bm + m0 + mm) * G4 + bn + n0];
        *(float4*)dst = r0;
        *(float4*)(dst + 4) = r1;
    }
}

// ---------------------------------------------------------------------------
// Phase B: persistent scan, 512 threads (16 warps), k split 8-way.
//   thread: kq=tid>>6 (0..7), r=tid&63: j=r>>3 (0..7), bg=r&7 -> b0=bg*4
//   smem: w_s dup pairs (131.3KB) + h_s [k][b] (64KB) + red scratch (28KB)
// ---------------------------------------------------------------------------
__global__ __launch_bounds__(512, 1) void lstm_scan(const float* __restrict__ Wh,
                                                    const float* __restrict__ bh,
                                                    float* __restrict__ out) {
    extern __shared__ float smem[];
    float* w_s = smem;                        // JPB * WJ floats
    float* h_s = smem + JPB * WJ;             // 512*32 floats
    float* red = h_s + Hsz * Bsz;             // 7*64*16 floats

    const int dir = blockIdx.x >> 6;
    const int sub = blockIdx.x & 63;
    const int j0 = sub * JPB;
    const int tid = threadIdx.x;
    const int kq = tid >> 6;       // 0..7
    const int r = tid & 63;
    const int j = r >> 3;          // 0..7
    const int bg = r & 7;          // 0..7
    const int b0 = bg * 4;
    const int k0 = kq * 64;

    // Load Wh tile once, duplicated (w,w) pairs per gate.
    for (int i = tid; i < JPB * 512; i += 512) {
        int j2 = i >> 9;
        int k = i & 511;
        float w0 = Wh[(size_t)(0 * Hsz + j0 + j2) * Hsz + k];
        float w1 = Wh[(size_t)(1 * Hsz + j0 + j2) * Hsz + k];
        float w2 = Wh[(size_t)(2 * Hsz + j0 + j2) * Hsz + k];
        float w3 = Wh[(size_t)(3 * Hsz + j0 + j2) * Hsz + k];
        float* d = &w_s[(size_t)j2 * WJ + k * 8];
        *(float4*)&d[0] = make_float4(w0, w0, w1, w1);
        *(float4*)&d[4] = make_float4(w2, w2, w3, w3);
    }

    float bh_g[4];
#pragma unroll
    for (int g = 0; g < 4; g++) bh_g[g] = bh[g * Hsz + j0 + j];

    unsigned* ctr = &g_ctr[dir][0];
    volatile unsigned* flag = &g_flag[dir][0];
    float cst[4] = {0.f, 0.f, 0.f, 0.f};
    __syncthreads();

    for (int t = 0; t < Tsz; t++) {
        const int te = dir ? (Tsz - 1 - t) : t;

        // Prefetch gx for owner threads (kq==0): 4 gates x 4 batches.
        float gxr[16];
        if (kq == 0) {
#pragma unroll
            for (int bb = 0; bb < 4; bb++) {
                const float* gp =
                    g_gx + ((size_t)(b0 + bb) * Tsz + te) * G4 + j0 + j;
#pragma unroll
                for (int g = 0; g < 4; g++)
                    gxr[g * 4 + bb] = __ldcg(gp + g * Hsz);
            }
        }

        // Stage h(t) into smem [k][b]: 8 float4 per thread.
        {
            const float4* src = (const float4*)&g_h[dir][t & 1][0];
            float4* dst = (float4*)h_s;
#pragma unroll 4
            for (int i = tid; i < (Hsz * Bsz) / 4; i += 512)
                dst[i] = __ldcg(src + i);
        }
        __syncthreads();

        // k-eighth GEMV. h batch-pairs are contiguous: load ulonglong2
        // directly, no pack movs.
        unsigned long long a00 = 0, a01 = 0, a10 = 0, a11 = 0;
        unsigned long long a20 = 0, a21 = 0, a30 = 0, a31 = 0;
        const ulonglong2* wp =
            (const ulonglong2*)&w_s[(size_t)j * WJ + k0 * 8];
        const ulonglong2* hp = (const ulonglong2*)&h_s[k0 * 32 + b0];
#pragma unroll 4
        for (int kk = 0; kk < 64; kk++) {
            ulonglong2 h2 = *hp;              // (h_b0,h_b1), (h_b2,h_b3)
            ulonglong2 wd01 = wp[0];          // (wi,wi), (wf,wf)
            ulonglong2 wd23 = wp[1];          // (wg,wg), (wo,wo)
            a00 = fma2(wd01.x, h2.x, a00);
            a01 = fma2(wd01.x, h2.y, a01);
            a10 = fma2(wd01.y, h2.x, a10);
            a11 = fma2(wd01.y, h2.y, a11);
            a20 = fma2(wd23.x, h2.x, a20);
            a21 = fma2(wd23.x, h2.y, a21);
            a30 = fma2(wd23.y, h2.x, a30);
            a31 = fma2(wd23.y, h2.y, a31);
            wp += 2;
            hp += 8;   // 128 bytes = next k row
        }

        // k-split partials to separate scratch (no sync needed before write).
        if (kq > 0) {
            ulonglong2* d = (ulonglong2*)&red[(size_t)((kq - 1) * 64 + r) * 16];
            d[0] = make_ulonglong2(a00, a01);
            d[1] = make_ulonglong2(a10, a11);
            d[2] = make_ulonglong2(a20, a21);
            d[3] = make_ulonglong2(a30, a31);
        }
        __syncthreads();

        if (kq == 0) {
#pragma unroll
            for (int p = 0; p < 7; p++) {
                const ulonglong2* s =
                    (const ulonglong2*)&red[(size_t)(p * 64 + r) * 16];
                ulonglong2 s0 = s[0], s1 = s[1], s2 = s[2], s3 = s[3];
                a00 = add2(a00, s0.x);
                a01 = add2(a01, s0.y);
                a10 = add2(a10, s1.x);
                a11 = add2(a11, s1.y);
                a20 = add2(a20, s2.x);
                a21 = add2(a21, s2.y);
                a30 = add2(a30, s3.x);
                a31 = add2(a31, s3.y);
            }
            float gate[4][4];
            float2 v;
            v = unpack2(a00); gate[0][0] = v.x; gate[0][1] = v.y;
            v = unpack2(a01); gate[0][2] = v.x; gate[0][3] = v.y;
            v = unpack2(a10); gate[1][0] = v.x; gate[1][1] = v.y;
            v = unpack2(a11); gate[1][2] = v.x; gate[1][3] = v.y;
            v = unpack2(a20); gate[2][0] = v.x; gate[2][1] = v.y;
            v = unpack2(a21); gate[2][2] = v.x; gate[2][3] = v.y;
            v = unpack2(a30); gate[3][0] = v.x; gate[3][1] = v.y;
            v = unpack2(a31); gate[3][2] = v.x; gate[3][3] = v.y;

            float hv[4];
#pragma unroll
            for (int bb = 0; bb < 4; bb++) {
                float gi = gate[0][bb] + gxr[0 * 4 + bb] + bh_g[0];
                float gf = gate[1][bb] + gxr[1 * 4 + bb] + bh_g[1];
                float gg = gate[2][bb] + gxr[2 * 4 + bb] + bh_g[2];
                float go = gate[3][bb] + gxr[3 * 4 + bb] + bh_g[3];
                float it = fast_sigmoid(gi);
                float ft = fast_sigmoid(gf);
                float gt = fast_tanh(gg);
                float ot = fast_sigmoid(go);
                cst[bb] = cst[bb] * ft + it * gt;
                hv[bb] = ot * fast_tanh(cst[bb]);
            }
            *(float4*)&g_h[dir][(t + 1) & 1][(j0 + j) * 32 + b0] =
                make_float4(hv[0], hv[1], hv[2], hv[3]);
#pragma unroll
            for (int bb = 0; bb < 4; bb++)
                out[((size_t)(b0 + bb) * Tsz + t) * (2 * Hsz) + dir * Hsz +
                    j0 + j] = hv[bb];
        }

        // Release h stores, then flag-based global barrier:
        // atomic on g_ctr (contended), poll on g_flag (clean line).
        __threadfence();
        __syncthreads();
        if (tid == 0) {
            unsigned old = atomicAdd(ctr, 1u);
            if (old == (unsigned)(NBLK_DIR * (t + 1)) - 1u) {
                __threadfence();
                *flag = (unsigned)(t + 1);     // release step t
            } else {
                while (*flag < (unsigned)(t + 1)) {
                }
            }
        }
        __syncthreads();
    }
}

// ---------------------------------------------------------------------------
extern "C" void kernel_launch(void* const* d_in, const int* in_sizes, int n_in,
                              void* d_out, int out_size) {
    const float* x = (const float*)d_in[0];   // (32,512,512)
    const float* Wx = (const float*)d_in[1];  // (2048,512)
    const float* bx = (const float*)d_in[2];  // (2048)
    const float* Wh = (const float*)d_in[3];  // (2048,512)
    const float* bh = (const float*)d_in[4];  // (2048)
    float* out = (float*)d_out;               // (32,512,1024)

    void* p_h = nullptr;
    void* p_ctr = nullptr;
    void* p_flag = nullptr;
    cudaGetSymbolAddress(&p_h, g_h);
    cudaGetSymbolAddress(&p_ctr, g_ctr);
    cudaGetSymbolAddress(&p_flag, g_flag);
    cudaMemsetAsync(p_h, 0, sizeof(g_h), 0);
    cudaMemsetAsync(p_ctr, 0, sizeof(g_ctr), 0);
    cudaMemsetAsync(p_flag, 0, sizeof(g_flag), 0);

    // Phase A: input projection GEMM (128x128 tiles).
    dim3 grid(G4 / 128, (Bsz * Tsz) / 128);
    gemm_gx<<<grid, 256>>>(x, Wx, bx);

    // Phase B: persistent scan.
    const int smem_bytes =
        (JPB * WJ + Hsz * Bsz + 7 * 64 * 16) * (int)sizeof(float);
    cudaFuncSetAttribute(lstm_scan, cudaFuncAttributeMaxDynamicSharedMemorySize,
                         smem_bytes);
    lstm_scan<<<2 * NBLK_DIR, 512, smem_bytes>>>(Wh, bh, out);
}

// round 11
// speedup vs baseline: 1.2468x; 1.2468x over previous
#include <cuda_runtime.h>
#include <cuda_bf16.h>
#include <cstdint>

// ---------------------------------------------------------------------------
// BiLSTM: B=32, T=512, I=512, H=512, gates=4H=2048, out (32,512,1024) fp32
//
// Phase A: gx = x @ Wx^T + bx. 128x128 tile, 8x8 micro-tile, K-tile 8,
//          double-buffered smem, f32x2 packed FMA (round-6 version).
// Phase B: persistent scan, 2 dirs x 64 blocks x 512 threads.
//          NO global barrier: producer-flag gated staging. Each block
//          release-publishes its 1KB h-slice flag; consumers' warps poll the
//          4 flags they own and copy those slices as soon as ready.
// ---------------------------------------------------------------------------

#define Bsz 32
#define Tsz 512
#define Isz 512
#define Hsz 512
#define G4  2048

#define JPB 8          // hidden units per block
#define NBLK_DIR 64    // blocks per direction
#define WJ 4104        // padded per-j stride in w_s (512*8 + 8 floats)

__device__ float g_gx[(size_t)Bsz * Tsz * G4];
__device__ float g_h[2][2][Hsz * Bsz];             // [dir][parity][j*32 + b]
__device__ __align__(128) unsigned g_pflag[2][NBLK_DIR][32];  // [dir][sub][0]

// ---- packed f32x2 helpers --------------------------------------------------
__device__ __forceinline__ unsigned long long fma2(unsigned long long a,
                                                   unsigned long long b,
                                                   unsigned long long c) {
    unsigned long long d;
    asm("fma.rn.f32x2 %0, %1, %2, %3;" : "=l"(d) : "l"(a), "l"(b), "l"(c));
    return d;
}
__device__ __forceinline__ unsigned long long add2(unsigned long long a,
                                                   unsigned long long b) {
    unsigned long long d;
    asm("add.rn.f32x2 %0, %1, %2;" : "=l"(d) : "l"(a), "l"(b));
    return d;
}
__device__ __forceinline__ unsigned long long pack2(float lo, float hi) {
    unsigned long long r;
    asm("mov.b64 %0, {%1, %2};" : "=l"(r) : "f"(lo), "f"(hi));
    return r;
}
__device__ __forceinline__ float2 unpack2(unsigned long long v) {
    float2 r;
    asm("mov.b64 {%0, %1}, %2;" : "=f"(r.x), "=f"(r.y) : "l"(v));
    return r;
}
__device__ __forceinline__ unsigned ld_acquire_gpu(const unsigned* p) {
    unsigned v;
    asm volatile("ld.acquire.gpu.global.u32 %0, [%1];" : "=r"(v) : "l"(p));
    return v;
}
__device__ __forceinline__ void st_relaxed_gpu(unsigned* p, unsigned v) {
    asm volatile("st.relaxed.gpu.global.u32 [%0], %1;" :: "l"(p), "r"(v));
}

__device__ __forceinline__ float fast_sigmoid(float x) {
    return __fdividef(1.0f, 1.0f + __expf(-x));
}
__device__ __forceinline__ float fast_tanh(float x) {
    return 1.0f - 2.0f * __fdividef(1.0f, __expf(2.0f * x) + 1.0f);
}

// ---------------------------------------------------------------------------
// Phase A: gx = x @ Wx^T + bx  (round-6 proven version)
// ---------------------------------------------------------------------------
__global__ __launch_bounds__(256, 2) void gemm_gx(const float* __restrict__ A,
                                                  const float* __restrict__ W,
                                                  const float* __restrict__ bx) {
    __shared__ __align__(16) float As[2][8][132];
    __shared__ __align__(16) float Bs[2][8][132];

    const int bm = blockIdx.y * 128;
    const int bn = blockIdx.x * 128;
    const int tid = threadIdx.x;
    const int lrow = tid >> 1;        // 0..127
    const int lkh = (tid & 1) * 4;    // 0 or 4
    const int ty = tid >> 4;          // 0..15
    const int tx = tid & 15;          // 0..15
    const int m0 = ty * 8;
    const int n0 = tx * 8;

    const float* Aptr = A + (size_t)(bm + lrow) * Isz + lkh;
    const float* Wptr = W + (size_t)(bn + lrow) * Isz + lkh;

    {
        float4 a = *(const float4*)Aptr;
        float4 w = *(const float4*)Wptr;
        As[0][lkh + 0][lrow] = a.x;
        As[0][lkh + 1][lrow] = a.y;
        As[0][lkh + 2][lrow] = a.z;
        As[0][lkh + 3][lrow] = a.w;
        Bs[0][lkh + 0][lrow] = w.x;
        Bs[0][lkh + 1][lrow] = w.y;
        Bs[0][lkh + 2][lrow] = w.z;
        Bs[0][lkh + 3][lrow] = w.w;
    }
    __syncthreads();

    unsigned long long acc[8][4];
#pragma unroll
    for (int i = 0; i < 8; i++)
#pragma unroll
        for (int q = 0; q < 4; q++) acc[i][q] = 0ull;

    int cur = 0;
    for (int kt = 1; kt <= 64; kt++) {
        float4 an = make_float4(0.f, 0.f, 0.f, 0.f);
        float4 wn = make_float4(0.f, 0.f, 0.f, 0.f);
        if (kt < 64) {
            an = *(const float4*)(Aptr + kt * 8);
            wn = *(const float4*)(Wptr + kt * 8);
        }
#pragma unroll
        for (int k = 0; k < 8; k++) {
            float4 aLo = *(const float4*)&As[cur][k][m0];
            float4 aHi = *(const float4*)&As[cur][k][m0 + 4];
            ulonglong2 bLo = *(const ulonglong2*)&Bs[cur][k][n0];
            ulonglong2 bHi = *(const ulonglong2*)&Bs[cur][k][n0 + 4];
            float am[8] = {aLo.x, aLo.y, aLo.z, aLo.w,
                           aHi.x, aHi.y, aHi.z, aHi.w};
#pragma unroll
            for (int mm = 0; mm < 8; mm++) {
                unsigned long long ad = pack2(am[mm], am[mm]);
                acc[mm][0] = fma2(bLo.x, ad, acc[mm][0]);
                acc[mm][1] = fma2(bLo.y, ad, acc[mm][1]);
                acc[mm][2] = fma2(bHi.x, ad, acc[mm][2]);
                acc[mm][3] = fma2(bHi.y, ad, acc[mm][3]);
            }
        }
        if (kt < 64) {
            int nxt = cur ^ 1;
            As[nxt][lkh + 0][lrow] = an.x;
            As[nxt][lkh + 1][lrow] = an.y;
            As[nxt][lkh + 2][lrow] = an.z;
            As[nxt][lkh + 3][lrow] = an.w;
            Bs[nxt][lkh + 0][lrow] = wn.x;
            Bs[nxt][lkh + 1][lrow] = wn.y;
            Bs[nxt][lkh + 2][lrow] = wn.z;
            Bs[nxt][lkh + 3][lrow] = wn.w;
        }
        __syncthreads();
        cur ^= 1;
    }

    float4 bxLo = *(const float4*)&bx[bn + n0];
    float4 bxHi = *(const float4*)&bx[bn + n0 + 4];
#pragma unroll
    for (int mm = 0; mm < 8; mm++) {
        float2 p0 = unpack2(acc[mm][0]);
        float2 p1 = unpack2(acc[mm][1]);
        float2 p2 = unpack2(acc[mm][2]);
        float2 p3 = unpack2(acc[mm][3]);
        float4 r0 = make_float4(p0.x + bxLo.x, p0.y + bxLo.y,
                                p1.x + bxLo.z, p1.y + bxLo.w);
        float4 r1 = make_float4(p2.x + bxHi.x, p2.y + bxHi.y,
                                p3.x + bxHi.z, p3.y + bxHi.w);
        float* dst = &g_gx[(size_t)(bm + m0 + mm) * G4 + bn + n0];
        *(float4*)dst = r0;
        *(float4*)(dst + 4) = r1;
    }
}

// ---------------------------------------------------------------------------
// Phase B: persistent scan, 512 threads, k split 8-way, flag-gated staging.
//   thread: kq=tid>>6 (0..7), r=tid&63: j=r>>3 (0..7), bg=r&7 -> b0=bg*4
//   smem: w_s dup pairs (131.3KB) + h_s [k][b] (64KB) + red scratch (28KB)
// Flag protocol: pflag[dir][sub] == v  means  h(v) slice of producer `sub`
// is published in g_h[dir][v&1]. Consumers poll >= t before copying h(t).
// ---------------------------------------------------------------------------
__global__ __launch_bounds__(512, 1) void lstm_scan(const float* __restrict__ Wh,
                                                    const float* __restrict__ bh,
                                                    float* __restrict__ out) {
    extern __shared__ float smem[];
    float* w_s = smem;                        // JPB * WJ floats
    float* h_s = smem + JPB * WJ;             // 512*32 floats
    float* red = h_s + Hsz * Bsz;             // 7*64*16 floats

    const int dir = blockIdx.x >> 6;
    const int sub = blockIdx.x & 63;
    const int j0 = sub * JPB;
    const int tid = threadIdx.x;
    const int w = tid >> 5;        // warp 0..15
    const int lane = tid & 31;
    const int kq = tid >> 6;       // 0..7
    const int r = tid & 63;
    const int j = r >> 3;          // 0..7
    const int bg = r & 7;          // 0..7
    const int b0 = bg * 4;
    const int k0 = kq * 64;

    // Load Wh tile once, duplicated (w,w) pairs per gate.
    for (int i = tid; i < JPB * 512; i += 512) {
        int j2 = i >> 9;
        int k = i & 511;
        float w0 = Wh[(size_t)(0 * Hsz + j0 + j2) * Hsz + k];
        float w1 = Wh[(size_t)(1 * Hsz + j0 + j2) * Hsz + k];
        float w2 = Wh[(size_t)(2 * Hsz + j0 + j2) * Hsz + k];
        float w3 = Wh[(size_t)(3 * Hsz + j0 + j2) * Hsz + k];
        float* d = &w_s[(size_t)j2 * WJ + k * 8];
        *(float4*)&d[0] = make_float4(w0, w0, w1, w1);
        *(float4*)&d[4] = make_float4(w2, w2, w3, w3);
    }

    float bh_g[4];
#pragma unroll
    for (int g = 0; g < 4; g++) bh_g[g] = bh[g * Hsz + j0 + j];

    float cst[4] = {0.f, 0.f, 0.f, 0.f};
    // Warp w stages producer slices p = 4w .. 4w+3 (1KB each, contiguous).
    const int p_base = w * 4;
    const unsigned* my_flag =
        (lane < 4) ? &g_pflag[dir][p_base + lane][0] : nullptr;
    unsigned* own_flag = &g_pflag[dir][sub][0];
    __syncthreads();

    for (int t = 0; t < Tsz; t++) {
        const int te = dir ? (Tsz - 1 - t) : t;

        // Prefetch gx for owner threads (kq==0): independent of h.
        float gxr[16];
        if (kq == 0) {
#pragma unroll
            for (int bb = 0; bb < 4; bb++) {
                const float* gp =
                    g_gx + ((size_t)(b0 + bb) * Tsz + te) * G4 + j0 + j;
#pragma unroll
                for (int g = 0; g < 4; g++)
                    gxr[g * 4 + bb] = __ldcg(gp + g * Hsz);
            }
        }

        // Flag-gated staging of h(t): wait for the 4 producers this warp
        // owns, then copy their 4KB into h_s. (t==0: flags start at 0.)
        {
            bool ready = (lane >= 4);
            if (!ready) ready = (ld_acquire_gpu(my_flag) >= (unsigned)t);
            while (!__all_sync(0xffffffffu, ready)) {
                if (!ready) ready = (ld_acquire_gpu(my_flag) >= (unsigned)t);
            }
            const float4* src =
                (const float4*)(&g_h[dir][t & 1][0] + p_base * (JPB * Bsz));
            float4* dst = (float4*)(h_s + p_base * (JPB * Bsz));
#pragma unroll
            for (int i = 0; i < 8; i++)
                dst[lane + 32 * i] = __ldcg(src + lane + 32 * i);
        }
        __syncthreads();

        // k-eighth GEMV: w dup pairs, h natural pairs -> no pack movs.
        unsigned long long a00 = 0, a01 = 0, a10 = 0, a11 = 0;
        unsigned long long a20 = 0, a21 = 0, a30 = 0, a31 = 0;
        const ulonglong2* wp =
            (const ulonglong2*)&w_s[(size_t)j * WJ + k0 * 8];
        const ulonglong2* hp = (const ulonglong2*)&h_s[k0 * 32 + b0];
#pragma unroll 4
        for (int kk = 0; kk < 64; kk++) {
            ulonglong2 h2 = *hp;
            ulonglong2 wd01 = wp[0];
            ulonglong2 wd23 = wp[1];
            a00 = fma2(wd01.x, h2.x, a00);
            a01 = fma2(wd01.x, h2.y, a01);
            a10 = fma2(wd01.y, h2.x, a10);
            a11 = fma2(wd01.y, h2.y, a11);
            a20 = fma2(wd23.x, h2.x, a20);
            a21 = fma2(wd23.x, h2.y, a21);
            a30 = fma2(wd23.y, h2.x, a30);
            a31 = fma2(wd23.y, h2.y, a31);
            wp += 2;
            hp += 8;
        }

        // Partials to separate scratch.
        if (kq > 0) {
            ulonglong2* d = (ulonglong2*)&red[(size_t)((kq - 1) * 64 + r) * 16];
            d[0] = make_ulonglong2(a00, a01);
            d[1] = make_ulonglong2(a10, a11);
            d[2] = make_ulonglong2(a20, a21);
            d[3] = make_ulonglong2(a30, a31);
        }
        __syncthreads();

        if (kq == 0) {
#pragma unroll
            for (int p = 0; p < 7; p++) {
                const ulonglong2* s =
                    (const ulonglong2*)&red[(size_t)(p * 64 + r) * 16];
                ulonglong2 s0 = s[0], s1 = s[1], s2 = s[2], s3 = s[3];
                a00 = add2(a00, s0.x);
                a01 = add2(a01, s0.y);
                a10 = add2(a10, s1.x);
                a11 = add2(a11, s1.y);
                a20 = add2(a20, s2.x);
                a21 = add2(a21, s2.y);
                a30 = add2(a30, s3.x);
                a31 = add2(a31, s3.y);
            }
            float gate[4][4];
            float2 v;
            v = unpack2(a00); gate[0][0] = v.x; gate[0][1] = v.y;
            v = unpack2(a01); gate[0][2] = v.x; gate[0][3] = v.y;
            v = unpack2(a10); gate[1][0] = v.x; gate[1][1] = v.y;
            v = unpack2(a11); gate[1][2] = v.x; gate[1][3] = v.y;
            v = unpack2(a20); gate[2][0] = v.x; gate[2][1] = v.y;
            v = unpack2(a21); gate[2][2] = v.x; gate[2][3] = v.y;
            v = unpack2(a30); gate[3][0] = v.x; gate[3][1] = v.y;
            v = unpack2(a31); gate[3][2] = v.x; gate[3][3] = v.y;

            float hv[4];
#pragma unroll
            for (int bb = 0; bb < 4; bb++) {
                float gi = gate[0][bb] + gxr[0 * 4 + bb] + bh_g[0];
                float gf = gate[1][bb] + gxr[1 * 4 + bb] + bh_g[1];
                float gg = gate[2][bb] + gxr[2 * 4 + bb] + bh_g[2];
                float go = gate[3][bb] + gxr[3 * 4 + bb] + bh_g[3];
                float it = fast_sigmoid(gi);
                float ft = fast_sigmoid(gf);
                float gt = fast_tanh(gg);
                float ot = fast_sigmoid(go);
                cst[bb] = cst[bb] * ft + it * gt;
                hv[bb] = ot * fast_tanh(cst[bb]);
            }
            // Publish h(t+1) slice.
            *(float4*)&g_h[dir][(t + 1) & 1][(j0 + j) * 32 + b0] =
                make_float4(hv[0], hv[1], hv[2], hv[3]);
#pragma unroll
            for (int bb = 0; bb < 4; bb++)
                out[((size_t)(b0 + bb) * Tsz + t) * (2 * Hsz) + dir * Hsz +
                    j0 + j] = hv[bb];
        }

        // Make the slice visible, then release-publish the flag. The
        // syncthreads gives CTA-scope happens-before from the owner stores
        // to tid0; tid0's fence makes them gpu-visible before the flag.
        __syncthreads();
        if (tid == 0) {
            __threadfence();
            st_relaxed_gpu(own_flag, (unsigned)(t + 1));
        }
    }
}

// ---------------------------------------------------------------------------
extern "C" void kernel_launch(void* const* d_in, const int* in_sizes, int n_in,
                              void* d_out, int out_size) {
    const float* x = (const float*)d_in[0];   // (32,512,512)
    const float* Wx = (const float*)d_in[1];  // (2048,512)
    const float* bx = (const float*)d_in[2];  // (2048)
    const float* Wh = (const float*)d_in[3];  // (2048,512)
    const float* bh = (const float*)d_in[4];  // (2048)
    float* out = (float*)d_out;               // (32,512,1024)

    void* p_h = nullptr;
    void* p_flag = nullptr;
    cudaGetSymbolAddress(&p_h, g_h);
    cudaGetSymbolAddress(&p_flag, g_pflag);
    cudaMemsetAsync(p_h, 0, sizeof(g_h), 0);
    cudaMemsetAsync(p_flag, 0, sizeof(g_pflag), 0);

    // Phase A: input projection GEMM (128x128 tiles).
    dim3 grid(G4 / 128, (Bsz * Tsz) / 128);
    gemm_gx<<<grid, 256>>>(x, Wx, bx);

    // Phase B: persistent scan.
    const int smem_bytes =
        (JPB * WJ + Hsz * Bsz + 7 * 64 * 16) * (int)sizeof(float);
    cudaFuncSetAttribute(lstm_scan, cudaFuncAttributeMaxDynamicSharedMemorySize,
                         smem_bytes);
    lstm_scan<<<2 * NBLK_DIR, 512, smem_bytes>>>(Wh, bh, out);
}

// round 12
// speedup vs baseline: 1.4104x; 1.1312x over previous
#include <cuda_runtime.h>
#include <cuda_bf16.h>
#include <cstdint>

// ---------------------------------------------------------------------------
// BiLSTM: B=32, T=512, I=512, H=512, gates=4H=2048, out (32,512,1024) fp32
//
// Phase A: gx = x @ Wx^T + bx. 128x128 tile, 8x8 micro-tile, K-tile 8,
//          double-buffered smem, f32x2 packed FMA (proven round-6 version).
// Phase B: persistent scan, 2 dirs x 64 blocks x 512 threads.
//          Warp-autonomous k-sixteenths: warp w owns k in [32w,32w+32) and
//          stages exactly the 4 producer slices it consumes -> no pre-GEMV
//          block sync. Micro-tile 1j x 4g x 8b (16 FFMA2 / 4 LDS.128).
//          Partials dumped warp-locally into the warp's own h_s region;
//          128-thread pairwise finalize. 2 syncthreads per step.
// ---------------------------------------------------------------------------

#define Bsz 32
#define Tsz 512
#define Isz 512
#define Hsz 512
#define G4  2048

#define JPB 8          // hidden units per block
#define NBLK_DIR 64    // blocks per direction
#define WJ 4100        // per-j stride in w_s floats: 4100*4 B == 16 mod 128
                       //   -> 8 j-broadcast addresses hit distinct bank quads

__device__ float g_gx[(size_t)Bsz * Tsz * G4];
__device__ float g_h[2][2][Hsz * Bsz];             // [dir][parity][j*32 + b]
__device__ __align__(128) unsigned g_pflag[2][NBLK_DIR][32];  // [dir][sub][0]

// ---- packed f32x2 helpers --------------------------------------------------
__device__ __forceinline__ unsigned long long fma2(unsigned long long a,
                                                   unsigned long long b,
                                                   unsigned long long c) {
    unsigned long long d;
    asm("fma.rn.f32x2 %0, %1, %2, %3;" : "=l"(d) : "l"(a), "l"(b), "l"(c));
    return d;
}
__device__ __forceinline__ unsigned long long add2(unsigned long long a,
                                                   unsigned long long b) {
    unsigned long long d;
    asm("add.rn.f32x2 %0, %1, %2;" : "=l"(d) : "l"(a), "l"(b));
    return d;
}
__device__ __forceinline__ unsigned long long pack2(float lo, float hi) {
    unsigned long long r;
    asm("mov.b64 %0, {%1, %2};" : "=l"(r) : "f"(lo), "f"(hi));
    return r;
}
__device__ __forceinline__ float2 unpack2(unsigned long long v) {
    float2 r;
    asm("mov.b64 {%0, %1}, %2;" : "=f"(r.x), "=f"(r.y) : "l"(v));
    return r;
}
__device__ __forceinline__ unsigned ld_acquire_gpu(const unsigned* p) {
    unsigned v;
    asm volatile("ld.acquire.gpu.global.u32 %0, [%1];" : "=r"(v) : "l"(p));
    return v;
}
__device__ __forceinline__ void st_relaxed_gpu(unsigned* p, unsigned v) {
    asm volatile("st.relaxed.gpu.global.u32 [%0], %1;" :: "l"(p), "r"(v));
}

__device__ __forceinline__ float fast_sigmoid(float x) {
    return __fdividef(1.0f, 1.0f + __expf(-x));
}
__device__ __forceinline__ float fast_tanh(float x) {
    return 1.0f - 2.0f * __fdividef(1.0f, __expf(2.0f * x) + 1.0f);
}

// ---------------------------------------------------------------------------
// Phase A: gx = x @ Wx^T + bx  (proven round-6 version)
// ---------------------------------------------------------------------------
__global__ __launch_bounds__(256, 2) void gemm_gx(const float* __restrict__ A,
                                                  const float* __restrict__ W,
                                                  const float* __restrict__ bx) {
    __shared__ __align__(16) float As[2][8][132];
    __shared__ __align__(16) float Bs[2][8][132];

    const int bm = blockIdx.y * 128;
    const int bn = blockIdx.x * 128;
    const int tid = threadIdx.x;
    const int lrow = tid >> 1;
    const int lkh = (tid & 1) * 4;
    const int ty = tid >> 4;
    const int tx = tid & 15;
    const int m0 = ty * 8;
    const int n0 = tx * 8;

    const float* Aptr = A + (size_t)(bm + lrow) * Isz + lkh;
    const float* Wptr = W + (size_t)(bn + lrow) * Isz + lkh;

    {
        float4 a = *(const float4*)Aptr;
        float4 w = *(const float4*)Wptr;
        As[0][lkh + 0][lrow] = a.x;
        As[0][lkh + 1][lrow] = a.y;
        As[0][lkh + 2][lrow] = a.z;
        As[0][lkh + 3][lrow] = a.w;
        Bs[0][lkh + 0][lrow] = w.x;
        Bs[0][lkh + 1][lrow] = w.y;
        Bs[0][lkh + 2][lrow] = w.z;
        Bs[0][lkh + 3][lrow] = w.w;
    }
    __syncthreads();

    unsigned long long acc[8][4];
#pragma unroll
    for (int i = 0; i < 8; i++)
#pragma unroll
        for (int q = 0; q < 4; q++) acc[i][q] = 0ull;

    int cur = 0;
    for (int kt = 1; kt <= 64; kt++) {
        float4 an = make_float4(0.f, 0.f, 0.f, 0.f);
        float4 wn = make_float4(0.f, 0.f, 0.f, 0.f);
        if (kt < 64) {
            an = *(const float4*)(Aptr + kt * 8);
            wn = *(const float4*)(Wptr + kt * 8);
        }
#pragma unroll
        for (int k = 0; k < 8; k++) {
            float4 aLo = *(const float4*)&As[cur][k][m0];
            float4 aHi = *(const float4*)&As[cur][k][m0 + 4];
            ulonglong2 bLo = *(const ulonglong2*)&Bs[cur][k][n0];
            ulonglong2 bHi = *(const ulonglong2*)&Bs[cur][k][n0 + 4];
            float am[8] = {aLo.x, aLo.y, aLo.z, aLo.w,
                           aHi.x, aHi.y, aHi.z, aHi.w};
#pragma unroll
            for (int mm = 0; mm < 8; mm++) {
                unsigned long long ad = pack2(am[mm], am[mm]);
                acc[mm][0] = fma2(bLo.x, ad, acc[mm][0]);
                acc[mm][1] = fma2(bLo.y, ad, acc[mm][1]);
                acc[mm][2] = fma2(bHi.x, ad, acc[mm][2]);
                acc[mm][3] = fma2(bHi.y, ad, acc[mm][3]);
            }
        }
        if (kt < 64) {
            int nxt = cur ^ 1;
            As[nxt][lkh + 0][lrow] = an.x;
            As[nxt][lkh + 1][lrow] = an.y;
            As[nxt][lkh + 2][lrow] = an.z;
            As[nxt][lkh + 3][lrow] = an.w;
            Bs[nxt][lkh + 0][lrow] = wn.x;
            Bs[nxt][lkh + 1][lrow] = wn.y;
            Bs[nxt][lkh + 2][lrow] = wn.z;
            Bs[nxt][lkh + 3][lrow] = wn.w;
        }
        __syncthreads();
        cur ^= 1;
    }

    float4 bxLo = *(const float4*)&bx[bn + n0];
    float4 bxHi = *(const float4*)&bx[bn + n0 + 4];
#pragma unroll
    for (int mm = 0; mm < 8; mm++) {
        float2 p0 = unpack2(acc[mm][0]);
        float2 p1 = unpack2(acc[mm][1]);
        float2 p2 = unpack2(acc[mm][2]);
        float2 p3 = unpack2(acc[mm][3]);
        float4 r0 = make_float4(p0.x + bxLo.x, p0.y + bxLo.y,
                                p1.x + bxLo.z, p1.y + bxLo.w);
        float4 r1 = make_float4(p2.x + bxHi.x, p2.y + bxHi.y,
                                p3.x + bxHi.z, p3.y + bxHi.w);
        float* dst = &g_gx[(size_t)(bm + m0 + mm) * G4 + bn + n0];
        *(float4*)dst = r0;
        *(float4*)(dst + 4) = r1;
    }
}

// ---------------------------------------------------------------------------
// Phase B scan.
// Warp w (0..15): k0 = 32w, stages producers 4w..4w+3 into its own h_s
// region [1024w, 1024w+1024) floats, GEMV there, dumps partials back into
// the same region (warp-local, no cross-warp smem use before the sync).
// Lane = (j 0..7)*4 + (bg 0..3); per lane: 1 j x 4 gates x 8 batches
// (b0 = 8*bg), 16 f32x2 accumulators.
// Finalize: 128 threads (j 0..7, bp 0..15): 16-way add2 reduction per gate,
// gx + bias + activations for batches (2bp, 2bp+1), publish h + out.
// smem: w_s 8*4100 floats (131.2KB) + h_s 16384 floats (64KB) = 196.7KB.
// ---------------------------------------------------------------------------
__global__ __launch_bounds__(512, 1) void lstm_scan(const float* __restrict__ Wh,
                                                    const float* __restrict__ bh,
                                                    float* __restrict__ out) {
    extern __shared__ float smem[];
    float* w_s = smem;                        // JPB * WJ floats
    float* h_s = smem + JPB * WJ;             // 512*32 floats (+ partials)

    const int dir = blockIdx.x >> 6;
    const int sub = blockIdx.x & 63;
    const int j0 = sub * JPB;
    const int tid = threadIdx.x;
    const int w = tid >> 5;        // warp 0..15 == k-sixteenth
    const int lane = tid & 31;
    const int j = lane >> 2;       // 0..7
    const int bg = lane & 3;       // 0..3
    const int b0 = bg * 8;
    const int k0 = w * 32;

    // Load Wh tile once, duplicated (w,w) pairs per gate:
    // w_s[j][k][8] = (wi,wi,wf,wf,wg,wg,wo,wo)
    for (int i = tid; i < JPB * 512; i += 512) {
        int j2 = i >> 9;
        int k = i & 511;
        float w0 = Wh[(size_t)(0 * Hsz + j0 + j2) * Hsz + k];
        float w1 = Wh[(size_t)(1 * Hsz + j0 + j2) * Hsz + k];
        float w2 = Wh[(size_t)(2 * Hsz + j0 + j2) * Hsz + k];
        float w3 = Wh[(size_t)(3 * Hsz + j0 + j2) * Hsz + k];
        float* d = &w_s[(size_t)j2 * WJ + k * 8];
        *(float4*)&d[0] = make_float4(w0, w0, w1, w1);
        *(float4*)&d[4] = make_float4(w2, w2, w3, w3);
    }

    // Finalize-thread statics (tid < 128): j_f = tid>>4, bp = tid&15.
    const int j_f = tid >> 4;
    const int bp = tid & 15;
    const int bg_f = bp >> 2;
    const int pp = bp & 3;
    const int bph = pp >> 1;
    const int sel = pp & 1;
    const int L = j_f * 4 + bg_f;
    float bh_g[4];
    if (tid < 128) {
#pragma unroll
        for (int g = 0; g < 4; g++) bh_g[g] = bh[g * Hsz + j0 + j_f];
    }
    float cst[2] = {0.f, 0.f};

    const unsigned* my_flag =
        (lane < 4) ? &g_pflag[dir][4 * w + lane][0] : nullptr;
    unsigned* own_flag = &g_pflag[dir][sub][0];
    __syncthreads();

    for (int t = 0; t < Tsz; t++) {
        const int te = dir ? (Tsz - 1 - t) : t;

        // ---- Warp-autonomous staging of own k-slice --------------------
        {
            bool ready = (lane >= 4);
            if (!ready) ready = (ld_acquire_gpu(my_flag) >= (unsigned)t);
            while (!__all_sync(0xffffffffu, ready)) {
                if (!ready) ready = (ld_acquire_gpu(my_flag) >= (unsigned)t);
            }
            const float4* src =
                (const float4*)&g_h[dir][t & 1][0] + 256 * w;
            float4* dst = (float4*)(h_s + 1024 * w);
#pragma unroll
            for (int i = 0; i < 8; i++)
                dst[lane + 32 * i] = __ldcg(src + lane + 32 * i);
        }

        // ---- k-sixteenth GEMV: 1j x 4g x 8b ----------------------------
        unsigned long long acc[4][4];
#pragma unroll
        for (int g = 0; g < 4; g++)
#pragma unroll
            for (int q = 0; q < 4; q++) acc[g][q] = 0ull;

        const ulonglong2* wp2 =
            (const ulonglong2*)(w_s + (size_t)j * WJ + k0 * 8);
        const ulonglong2* hp2 = (const ulonglong2*)(h_s + k0 * 32 + b0);
#pragma unroll 4
        for (int kk = 0; kk < 32; kk++) {
            ulonglong2 hAB = hp2[0];     // (b0,b0+1),(b0+2,b0+3)
            ulonglong2 hCD = hp2[1];     // (b0+4,b0+5),(b0+6,b0+7)
            ulonglong2 wd01 = wp2[0];    // (wi,wi),(wf,wf)
            ulonglong2 wd23 = wp2[1];    // (wg,wg),(wo,wo)
            acc[0][0] = fma2(wd01.x, hAB.x, acc[0][0]);
            acc[0][1] = fma2(wd01.x, hAB.y, acc[0][1]);
            acc[0][2] = fma2(wd01.x, hCD.x, acc[0][2]);
            acc[0][3] = fma2(wd01.x, hCD.y, acc[0][3]);
            acc[1][0] = fma2(wd01.y, hAB.x, acc[1][0]);
            acc[1][1] = fma2(wd01.y, hAB.y, acc[1][1]);
            acc[1][2] = fma2(wd01.y, hCD.x, acc[1][2]);
            acc[1][3] = fma2(wd01.y, hCD.y, acc[1][3]);
            acc[2][0] = fma2(wd23.x, hAB.x, acc[2][0]);
            acc[2][1] = fma2(wd23.x, hAB.y, acc[2][1]);
            acc[2][2] = fma2(wd23.x, hCD.x, acc[2][2]);
            acc[2][3] = fma2(wd23.x, hCD.y, acc[2][3]);
            acc[3][0] = fma2(wd23.y, hAB.x, acc[3][0]);
            acc[3][1] = fma2(wd23.y, hAB.y, acc[3][1]);
            acc[3][2] = fma2(wd23.y, hCD.x, acc[3][2]);
            acc[3][3] = fma2(wd23.y, hCD.y, acc[3][3]);
            wp2 += 2;
            hp2 += 8;
        }

        // ---- Dump partials into own region (warp-local, no sync) -------
        // Layout in region w: ull2 index (g*2 + bph)*32 + lane.
        {
            ulonglong2* rd = (ulonglong2*)(h_s + 1024 * w);
#pragma unroll
            for (int g = 0; g < 4; g++) {
                rd[(g * 2 + 0) * 32 + lane] =
                    make_ulonglong2(acc[g][0], acc[g][1]);
                rd[(g * 2 + 1) * 32 + lane] =
                    make_ulonglong2(acc[g][2], acc[g][3]);
            }
        }

        // gx prefetch for finalize threads (in flight across the barrier).
        float gxr[8];
        if (tid < 128) {
#pragma unroll
            for (int g = 0; g < 4; g++) {
                const float* gp =
                    g_gx + ((size_t)(2 * bp) * Tsz + te) * G4 + g * Hsz +
                    j0 + j_f;
                gxr[g * 2 + 0] = __ldcg(gp);
                gxr[g * 2 + 1] = __ldcg(gp + (size_t)Tsz * G4);
            }
        }
        __syncthreads();   // all partials visible

        // ---- Finalize: 16-way reduce + cell update (128 threads) -------
        if (tid < 128) {
            unsigned long long gate[4];
#pragma unroll
            for (int g = 0; g < 4; g++) {
                const int off = ((g * 2 + bph) * 32 + L) * 4 + sel * 2;
                unsigned long long s = 0ull;
#pragma unroll
                for (int ww = 0; ww < 16; ww++)
                    s = add2(s, *(const unsigned long long*)
                                    &h_s[ww * 1024 + off]);
                gate[g] = s;
            }
            float2 gi2 = unpack2(gate[0]);
            float2 gf2 = unpack2(gate[1]);
            float2 gg2 = unpack2(gate[2]);
            float2 go2 = unpack2(gate[3]);
            float gi[2] = {gi2.x, gi2.y};
            float gf[2] = {gf2.x, gf2.y};
            float gg[2] = {gg2.x, gg2.y};
            float go[2] = {go2.x, go2.y};
            float hv[2];
#pragma unroll
            for (int bi = 0; bi < 2; bi++) {
                float vi = gi[bi] + gxr[0 * 2 + bi] + bh_g[0];
                float vf = gf[bi] + gxr[1 * 2 + bi] + bh_g[1];
                float vg = gg[bi] + gxr[2 * 2 + bi] + bh_g[2];
                float vo = go[bi] + gxr[3 * 2 + bi] + bh_g[3];
                float it = fast_sigmoid(vi);
                float ft = fast_sigmoid(vf);
                float gt = fast_tanh(vg);
                float ot = fast_sigmoid(vo);
                cst[bi] = cst[bi] * ft + it * gt;
                hv[bi] = ot * fast_tanh(cst[bi]);
            }
            // Publish h(t+1) (8B store) + outputs.
            *(float2*)&g_h[dir][(t + 1) & 1][(j0 + j_f) * 32 + 2 * bp] =
                make_float2(hv[0], hv[1]);
            out[((size_t)(2 * bp) * Tsz + t) * (2 * Hsz) + dir * Hsz + j0 +
                j_f] = hv[0];
            out[((size_t)(2 * bp + 1) * Tsz + t) * (2 * Hsz) + dir * Hsz +
                j0 + j_f] = hv[1];
        }

        __syncthreads();   // finalize reads/writes done before next staging
        if (tid == 0) {
            __threadfence();
            st_relaxed_gpu(own_flag, (unsigned)(t + 1));
        }
    }
}

// ---------------------------------------------------------------------------
extern "C" void kernel_launch(void* const* d_in, const int* in_sizes, int n_in,
                              void* d_out, int out_size) {
    const float* x = (const float*)d_in[0];   // (32,512,512)
    const float* Wx = (const float*)d_in[1];  // (2048,512)
    const float* bx = (const float*)d_in[2];  // (2048)
    const float* Wh = (const float*)d_in[3];  // (2048,512)
    const float* bh = (const float*)d_in[4];  // (2048)
    float* out = (float*)d_out;               // (32,512,1024)

    void* p_h = nullptr;
    void* p_flag = nullptr;
    cudaGetSymbolAddress(&p_h, g_h);
    cudaGetSymbolAddress(&p_flag, g_pflag);
    cudaMemsetAsync(p_h, 0, sizeof(g_h), 0);
    cudaMemsetAsync(p_flag, 0, sizeof(g_pflag), 0);

    // Phase A: input projection GEMM (128x128 tiles).
    dim3 grid(G4 / 128, (Bsz * Tsz) / 128);
    gemm_gx<<<grid, 256>>>(x, Wx, bx);

    // Phase B: persistent scan.
    const int smem_bytes = (JPB * WJ + Hsz * Bsz) * (int)sizeof(float);
    cudaFuncSetAttribute(lstm_scan, cudaFuncAttributeMaxDynamicSharedMemorySize,
                         smem_bytes);
    lstm_scan<<<2 * NBLK_DIR, 512, smem_bytes>>>(Wh, bh, out);
}